// round 15
// baseline (speedup 1.0000x reference)
#include <cuda_runtime.h>
#include <cuda_fp16.h>
#include <cstdint>

#define NB 2
#define NS 2048
#define ND 1024
#define NH 16
#define NHD 64

// fp16 copies of the inputs (filled by cvt_kernel)
__device__ __half g_hQin[NB * NS * ND];
__device__ __half g_hKin[NB * NS * ND];
__device__ __half g_hWq[ND * ND];
__device__ __half g_hWk[ND * ND];

// Scratch — Q/K projections stored as fp16 (Q pre-scaled by 0.125*log2e).
__device__ __half g_Q[NB * NH * NS * NHD];
__device__ __half g_K[NB * NH * NS * NHD];
__device__ __half g_E[(size_t)NB * NH * NS * NS];     // 268 MB fp16 2^scores
__device__ float  g_Linv[NB * NH * NS];               // 1/(16*rowsum)
__device__ int    g_ctr[NB * 16];                     // per-(b,qtile) arrivals

// ---------------------------------------------------------------------------
__device__ __forceinline__ uint32_t smem_u32(const void* p) {
    uint32_t a;
    asm("{ .reg .u64 t; cvta.to.shared.u64 t, %1; cvt.u32.u64 %0, t; }"
        : "=r"(a) : "l"(p));
    return a;
}
__device__ __forceinline__ void cp16(uint32_t s, const void* g) {
    asm volatile("cp.async.cg.shared.global [%0], [%1], 16;" :: "r"(s), "l"(g));
}
#define CP_COMMIT() asm volatile("cp.async.commit_group;" ::: "memory")
#define CP_WAIT1()  asm volatile("cp.async.wait_group 1;" ::: "memory")
#define CP_WAIT0()  asm volatile("cp.async.wait_group 0;" ::: "memory")

__device__ __forceinline__ float ex2a(float x) {
    float y;
    asm("ex2.approx.f32 %0, %1;" : "=f"(y) : "f"(x));
    return y;
}

#define MMA_F16(d, a, b0, b1)                                                  \
    asm volatile(                                                              \
        "mma.sync.aligned.m16n8k16.row.col.f32.f16.f16.f32 "                   \
        "{%0,%1,%2,%3}, {%4,%5,%6,%7}, {%8,%9}, {%0,%1,%2,%3};"                \
        : "+f"((d)[0]), "+f"((d)[1]), "+f"((d)[2]), "+f"((d)[3])               \
        : "r"((a)[0]), "r"((a)[1]), "r"((a)[2]), "r"((a)[3]),                  \
          "r"(b0), "r"(b1))

#define LDSM_X4(r, addr)                                                       \
    asm volatile("ldmatrix.sync.aligned.m8n8.x4.shared.b16 {%0,%1,%2,%3}, [%4];" \
        : "=r"((r)[0]), "=r"((r)[1]), "=r"((r)[2]), "=r"((r)[3]) : "r"(addr))

#define STSM_X4(addr, r0, r1, r2, r3)                                          \
    asm volatile("stmatrix.sync.aligned.m8n8.x4.shared.b16 [%0], {%1,%2,%3,%4};" \
        :: "r"(addr), "r"(r0), "r"(r1), "r"(r2), "r"(r3) : "memory")

#define ONES2 0x3C003C00u
#define QSCALE 0.18033688011112042f

// ---------------------------------------------------------------------------
// cvt kernel: fp32 inputs -> fp16 buffers.
// ---------------------------------------------------------------------------
#define CVT_TOTAL (NB * NS * ND * 2 + ND * ND * 2)

__global__ __launch_bounds__(256) void cvt_kernel(
    const float* __restrict__ q, const float* __restrict__ k,
    const float* __restrict__ wq, const float* __restrict__ wk)
{
    const int idx = (blockIdx.x * 256 + threadIdx.x) * 8;
    const float* src;
    __half* dst;
    int off;
    if (idx < NB * NS * ND) {
        src = q; dst = g_hQin; off = idx;
    } else if (idx < 2 * NB * NS * ND) {
        src = k; dst = g_hKin; off = idx - NB * NS * ND;
    } else if (idx < 2 * NB * NS * ND + ND * ND) {
        src = wq; dst = g_hWq; off = idx - 2 * NB * NS * ND;
    } else {
        src = wk; dst = g_hWk; off = idx - 2 * NB * NS * ND - ND * ND;
    }
    float4 f0 = *(const float4*)(src + off);
    float4 f1 = *(const float4*)(src + off + 4);
    uint2 o0, o1;
    *(__half2*)&o0.x = __floats2half2_rn(f0.x, f0.y);
    *(__half2*)&o0.y = __floats2half2_rn(f0.z, f0.w);
    *(__half2*)&o1.x = __floats2half2_rn(f1.x, f1.y);
    *(__half2*)&o1.y = __floats2half2_rn(f1.z, f1.w);
    *(uint4*)(dst + off) = make_uint4(o0.x, o0.y, o1.x, o1.y);
}

// ---------------------------------------------------------------------------
// Projection GEMM (fp16 mma + ldmatrix, 4x2 warp layout) — unchanged R13.
// ---------------------------------------------------------------------------
#define PJ_H 40
#define PJ_BUF (128 * PJ_H)
#define PJ_SMEM_TOTAL (4 * PJ_BUF * 2)                 // 40,960 B

__global__ __launch_bounds__(256, 2) void proj_mma_kernel(
    const float* __restrict__ bq_in, const float* __restrict__ bk_in)
{
    const int z = blockIdx.z;
    const __half* __restrict__ X = z ? g_hKin : g_hQin;
    const __half* __restrict__ W = z ? g_hWk : g_hWq;
    const float* __restrict__ bias = z ? bk_in : bq_in;
    const float scale = z ? 1.0f : QSCALE;
    __half* __restrict__ Out = z ? g_K : g_Q;

    extern __shared__ __half pjs[];
    __half* Xs = pjs;
    __half* Ws = pjs + 2 * PJ_BUF;
    const uint32_t sb_x = smem_u32(Xs);
    const uint32_t sb_w = smem_u32(Ws);

    const int tid = threadIdx.x;
    const int lane = tid & 31, wid = tid >> 5;
    const int lq = lane & 3, lg = lane >> 2;
    const int wm = wid >> 1, wn = wid & 1;
    const int n0 = blockIdx.x * 128, m0 = blockIdx.y * 128;

    const int lrow = (lane & 7) + ((lane >> 3) & 1) * 8;
    const int lrowB = (lane & 7) + ((lane >> 4) & 1) * 8;
    const uint32_t lofA0 = (uint32_t)(((wm * 32 + lrow) * PJ_H + ((lane >> 4) & 1) * 8) * 2);
    const uint32_t lofA1 = (uint32_t)(((wm * 32 + 16 + lrow) * PJ_H + ((lane >> 4) & 1) * 8) * 2);
    const uint32_t lofB = (uint32_t)(((wn * 64 + lrowB) * PJ_H + ((lane >> 3) & 1) * 8) * 2);

    auto prefetch = [&](int st, int kb) {
        if (tid < 128) {
            uint32_t xs = sb_x + (uint32_t)((st * PJ_BUF + tid * PJ_H) * 2);
            const __half* xg = X + (size_t)(m0 + tid) * ND + kb;
#pragma unroll
            for (int i = 0; i < 4; i++) cp16(xs + i * 16, xg + i * 8);
        } else {
            int r = tid - 128;
            uint32_t ws = sb_w + (uint32_t)((st * PJ_BUF + r * PJ_H) * 2);
            const __half* wg = W + (size_t)(n0 + r) * ND + kb;
#pragma unroll
            for (int i = 0; i < 4; i++) cp16(ws + i * 16, wg + i * 8);
        }
    };

    float acc[2][8][4];
#pragma unroll
    for (int mt = 0; mt < 2; mt++)
#pragma unroll
        for (int nt = 0; nt < 8; nt++)
#pragma unroll
            for (int j = 0; j < 4; j++) acc[mt][nt][j] = 0.0f;

    prefetch(0, 0);
    CP_COMMIT();

    for (int kb_i = 0; kb_i < ND / 32; kb_i++) {
        if (kb_i + 1 < ND / 32) prefetch((kb_i + 1) & 1, (kb_i + 1) * 32);
        CP_COMMIT();
        CP_WAIT1();
        __syncthreads();

        const uint32_t xb = sb_x + (uint32_t)((kb_i & 1) * PJ_BUF * 2);
        const uint32_t wb = sb_w + (uint32_t)((kb_i & 1) * PJ_BUF * 2) + lofB;
#pragma unroll
        for (int s = 0; s < 2; s++) {
            uint32_t a0[4], a1[4];
            LDSM_X4(a0, xb + lofA0 + s * 32);
            LDSM_X4(a1, xb + lofA1 + s * 32);
#pragma unroll
            for (int ntp = 0; ntp < 4; ntp++) {
                uint32_t b[4];
                LDSM_X4(b, wb + ntp * (16 * PJ_H * 2) + s * 32);
                MMA_F16(acc[0][2 * ntp], a0, b[0], b[1]);
                MMA_F16(acc[0][2 * ntp + 1], a0, b[2], b[3]);
                MMA_F16(acc[1][2 * ntp], a1, b[0], b[1]);
                MMA_F16(acc[1][2 * ntp + 1], a1, b[2], b[3]);
            }
        }
        __syncthreads();
    }

#pragma unroll
    for (int mt = 0; mt < 2; mt++) {
        const int m_lo = m0 + wm * 32 + mt * 16 + lg;
        const int b_lo = m_lo >> 11, s_lo = m_lo & 2047;
        const int m_hi = m_lo + 8;
        const int b_hi = m_hi >> 11, s_hi = m_hi & 2047;
#pragma unroll
        for (int nt = 0; nt < 8; nt++) {
            int n = n0 + wn * 64 + nt * 8 + 2 * lq;
            float2 bb = *(const float2*)&bias[n];
            int h = n >> 6, hd = n & 63;
            __half2 o0 = __floats2half2_rn((acc[mt][nt][0] + bb.x) * scale,
                                           (acc[mt][nt][1] + bb.y) * scale);
            __half2 o1 = __floats2half2_rn((acc[mt][nt][2] + bb.x) * scale,
                                           (acc[mt][nt][3] + bb.y) * scale);
            *(__half2*)&Out[((size_t)(b_lo * NH + h) * NS + s_lo) * NHD + hd] = o0;
            *(__half2*)&Out[((size_t)(b_hi * NH + h) * NS + s_hi) * NHD + hd] = o1;
        }
    }
}

// ---------------------------------------------------------------------------
// Score kernel + fused finalize.
//   1-D grid, bid = ((b*16 + qt)*16 + h); groups of 16 consecutive CTAs share
//   (b, qt). Last arriver of each group reduces E over heads -> out (L2-warm).
// SMEM: Qs[128][72]h | Ks[2][128][72]h | stg[8][32][72]h   = 92,160 B
// ---------------------------------------------------------------------------
#define QS_H 72
#define KS_OFF  (128 * QS_H * 2)
#define STG_OFF (KS_OFF + 2 * 128 * QS_H * 2)
#define ST2 72
#define SC_SMEM_TOTAL (STG_OFF + 8 * 32 * ST2 * 2)     // 92,160 B

__global__ __launch_bounds__(256, 2) void score_kernel(float* __restrict__ out)
{
    extern __shared__ char smem[];
    __half* Qs = (__half*)smem;
    __half* Ks = (__half*)(smem + KS_OFF);
    __half* stgall = (__half*)(smem + STG_OFF);
    const uint32_t sb_q = smem_u32(Qs);
    const uint32_t sb_k = smem_u32(Ks);
    __shared__ int s_old;

    const int tid = threadIdx.x;
    const int lane = tid & 31;
    const int wid = tid >> 5;
    const int lq = lane & 3;
    const int lg = lane >> 2;
    const int wm = wid >> 1, wn = wid & 1;

    const int bid = blockIdx.x;
    const int grp = bid >> 4;                 // (b*16 + qt)
    const int h = bid & 15;
    const int bh = (grp >> 4) * NH + h;
    const int q0 = (grp & 15) * 128;

    __half* stgw = stgall + wid * 32 * ST2;

    const int lrowA = (lane & 7) + ((lane >> 3) & 1) * 8;
    const int lrowB = (lane & 7) + ((lane >> 4) & 1) * 8;
    const uint32_t lofA0 = (uint32_t)(((wm * 32 + lrowA) * QS_H + ((lane >> 4) & 1) * 8) * 2);
    const uint32_t lofA1 = (uint32_t)(((wm * 32 + 16 + lrowA) * QS_H + ((lane >> 4) & 1) * 8) * 2);
    const uint32_t lofB = (uint32_t)(((wn * 64 + lrowB) * QS_H + ((lane >> 3) & 1) * 8) * 2);
    const uint32_t sb_stg = smem_u32(stgw)
        + (uint32_t)((((lane & 7) + ((lane >> 4) & 1) * 8) * ST2
                      + ((lane >> 3) & 1) * 8) * 2);

    const int r_ld = tid >> 1;
    const int c_ld = (tid & 1) * 32;
    auto prefetchK = [&](int st, int kt) {
        uint32_t ks = sb_k + (uint32_t)((st * 128 * QS_H + r_ld * QS_H + c_ld) * 2);
        const __half* kg = g_K + ((size_t)bh * NS + kt * 128 + r_ld) * NHD + c_ld;
#pragma unroll
        for (int i = 0; i < 4; i++) cp16(ks + i * 16, kg + i * 8);
    };

    prefetchK(0, 0);
    CP_COMMIT();
    {
        uint32_t qs = sb_q + (uint32_t)((r_ld * QS_H + c_ld) * 2);
        const __half* qg = g_Q + ((size_t)bh * NS + q0 + r_ld) * NHD + c_ld;
#pragma unroll
        for (int i = 0; i < 4; i++) cp16(qs + i * 16, qg + i * 8);
    }
    CP_COMMIT();
    CP_WAIT0();
    __syncthreads();

    uint32_t afr[4][2][4];
#pragma unroll
    for (int s = 0; s < 4; s++) {
        LDSM_X4(afr[s][0], sb_q + lofA0 + s * 32);
        LDSM_X4(afr[s][1], sb_q + lofA1 + s * 32);
    }

    float accrs[2][4];
#pragma unroll
    for (int mt = 0; mt < 2; mt++)
#pragma unroll
        for (int j = 0; j < 4; j++) accrs[mt][j] = 0.0f;

    for (int kt = 0; kt < NS / 128; kt++) {
        if (kt + 1 < NS / 128) prefetchK((kt + 1) & 1, kt + 1);
        CP_COMMIT();
        CP_WAIT1();
        __syncthreads();

        const uint32_t kb = sb_k + (uint32_t)((kt & 1) * 128 * QS_H * 2) + lofB;

        float acc[2][8][4];
#pragma unroll
        for (int mt = 0; mt < 2; mt++)
#pragma unroll
            for (int nt = 0; nt < 8; nt++)
#pragma unroll
                for (int j = 0; j < 4; j++) acc[mt][nt][j] = 0.0f;

#pragma unroll
        for (int s = 0; s < 4; s++) {
#pragma unroll
            for (int ntp = 0; ntp < 4; ntp++) {
                uint32_t b[4];
                LDSM_X4(b, kb + ntp * (16 * QS_H * 2) + s * 32);
                MMA_F16(acc[0][2 * ntp], afr[s][0], b[0], b[1]);
                MMA_F16(acc[0][2 * ntp + 1], afr[s][0], b[2], b[3]);
                MMA_F16(acc[1][2 * ntp], afr[s][1], b[0], b[1]);
                MMA_F16(acc[1][2 * ntp + 1], afr[s][1], b[2], b[3]);
            }
        }

#pragma unroll
        for (int mt = 0; mt < 2; mt++) {
            uint32_t h2[16];
#pragma unroll
            for (int nt = 0; nt < 8; nt++) {
                float e0 = ex2a(acc[mt][nt][0]);
                float e1 = ex2a(acc[mt][nt][1]);
                float e2 = ex2a(acc[mt][nt][2]);
                float e3 = ex2a(acc[mt][nt][3]);
                __half2 ha = __floats2half2_rn(e0, e1);
                __half2 hb = __floats2half2_rn(e2, e3);
                h2[2 * nt] = *(uint32_t*)&ha;
                h2[2 * nt + 1] = *(uint32_t*)&hb;
            }
#pragma unroll
            for (int p = 0; p < 4; p++) {
                uint32_t a[4] = {h2[4 * p], h2[4 * p + 1],
                                 h2[4 * p + 2], h2[4 * p + 3]};
                MMA_F16(accrs[mt], a, ONES2, ONES2);
            }
#pragma unroll
            for (int p = 0; p < 4; p++) {
                STSM_X4(sb_stg + (uint32_t)(mt * 16 * ST2 * 2) + p * 32,
                        h2[4 * p], h2[4 * p + 2],
                        h2[4 * p + 1], h2[4 * p + 3]);
            }
        }
        __syncwarp();
#pragma unroll
        for (int rr = 0; rr < 8; rr++) {
            int row = rr * 4 + (lane >> 3);
            uint4 v = *(uint4*)&stgw[row * ST2 + (lane & 7) * 8];
            *(uint4*)&g_E[((size_t)bh * NS + q0 + wm * 32 + row) * NS
                          + kt * 128 + wn * 64 + (lane & 7) * 8] = v;
        }
        __syncthreads();
    }

    // Combine wn-partials; write Linv (with /16 folded).
    float* rsb = (float*)stgall;
    if (lq == 0) {
#pragma unroll
        for (int mt = 0; mt < 2; mt++) {
            int r = wm * 32 + mt * 16 + lg;
            rsb[wn * 128 + r] = accrs[mt][0];
            rsb[wn * 128 + r + 8] = accrs[mt][2];
        }
    }
    __syncthreads();
    if (tid < 128) {
        g_Linv[bh * NS + q0 + tid] = 0.0625f / (rsb[tid] + rsb[128 + tid]);
    }

    // ---- fused finalize: 16th arriver of this (b, qt) group reduces E ----
    __threadfence();
    __syncthreads();
    if (tid == 0) s_old = atomicAdd(&g_ctr[grp], 1);
    __syncthreads();
    if (s_old == 15) {
        __threadfence();
        const int bb = grp >> 4;
        const int qb = (grp & 15) * 128;
        for (int r = 0; r < 128; r++) {
            const int q = qb + r;
            float acc[8];
#pragma unroll
            for (int j = 0; j < 8; j++) acc[j] = 0.0f;
#pragma unroll
            for (int hh = 0; hh < NH; hh++) {
                const int bhh = bb * NH + hh;
                const float w = g_Linv[(bhh << 11) + q];
                uint4 v = *((const uint4*)(g_E + ((size_t)bhh * NS + q) * NS) + tid);
                const __half2* hp = (const __half2*)&v;
#pragma unroll
                for (int j = 0; j < 4; j++) {
                    float2 f = __half22float2(hp[j]);
                    acc[2 * j] += f.x * w;
                    acc[2 * j + 1] += f.y * w;
                }
            }
            float4* Op = (float4*)(out + ((size_t)bb * NS + q) * NS);
            Op[tid * 2 + 0] = make_float4(acc[0], acc[1], acc[2], acc[3]);
            Op[tid * 2 + 1] = make_float4(acc[4], acc[5], acc[6], acc[7]);
        }
        if (tid == 0) g_ctr[grp] = 0;    // reset for next graph replay
    }
}

// ---------------------------------------------------------------------------
extern "C" void kernel_launch(void* const* d_in, const int* in_sizes, int n_in,
                              void* d_out, int out_size)
{
    const float* query = (const float*)d_in[0];
    const float* key   = (const float*)d_in[1];
    const float* Wq    = (const float*)d_in[2];
    const float* bq    = (const float*)d_in[3];
    const float* Wk    = (const float*)d_in[4];
    const float* bk    = (const float*)d_in[5];
    float* out = (float*)d_out;

    cudaFuncSetAttribute(proj_mma_kernel,
                         cudaFuncAttributeMaxDynamicSharedMemorySize,
                         PJ_SMEM_TOTAL);
    cudaFuncSetAttribute(score_kernel,
                         cudaFuncAttributeMaxDynamicSharedMemorySize,
                         SC_SMEM_TOTAL);

    cvt_kernel<<<CVT_TOTAL / (256 * 8), 256>>>(query, key, Wq, Wk);
    proj_mma_kernel<<<dim3(ND / 128, (NB * NS) / 128, 2), 256, PJ_SMEM_TOTAL>>>(bq, bk);
    score_kernel<<<NB * 16 * 16, 256, SC_SMEM_TOTAL>>>(out);
}

// round 16
// speedup vs baseline: 1.6439x; 1.6439x over previous
#include <cuda_runtime.h>
#include <cuda_fp16.h>
#include <cstdint>

#define NB 2
#define NS 2048
#define ND 1024
#define NH 16
#define NHD 64

// fp16 copies of the inputs (filled by cvt_kernel)
__device__ __half g_hQin[NB * NS * ND];
__device__ __half g_hKin[NB * NS * ND];
__device__ __half g_hWq[ND * ND];
__device__ __half g_hWk[ND * ND];

// Scratch — Q/K projections stored as fp16 (Q pre-scaled by 0.125*log2e).
__device__ __half g_Q[NB * NH * NS * NHD];
__device__ __half g_K[NB * NH * NS * NHD];
__device__ __half g_E[(size_t)NB * NH * NS * NS];     // 268 MB fp16 2^scores
__device__ float  g_Linv[NB * NH * NS];               // 1/(16*rowsum)

// ---------------------------------------------------------------------------
__device__ __forceinline__ uint32_t smem_u32(const void* p) {
    uint32_t a;
    asm("{ .reg .u64 t; cvta.to.shared.u64 t, %1; cvt.u32.u64 %0, t; }"
        : "=r"(a) : "l"(p));
    return a;
}
__device__ __forceinline__ void cp16(uint32_t s, const void* g) {
    asm volatile("cp.async.cg.shared.global [%0], [%1], 16;" :: "r"(s), "l"(g));
}
#define CP_COMMIT() asm volatile("cp.async.commit_group;" ::: "memory")
#define CP_WAIT1()  asm volatile("cp.async.wait_group 1;" ::: "memory")
#define CP_WAIT0()  asm volatile("cp.async.wait_group 0;" ::: "memory")

__device__ __forceinline__ float ex2a(float x) {
    float y;
    asm("ex2.approx.f32 %0, %1;" : "=f"(y) : "f"(x));
    return y;
}

#define MMA_F16(d, a, b0, b1)                                                  \
    asm volatile(                                                              \
        "mma.sync.aligned.m16n8k16.row.col.f32.f16.f16.f32 "                   \
        "{%0,%1,%2,%3}, {%4,%5,%6,%7}, {%8,%9}, {%0,%1,%2,%3};"                \
        : "+f"((d)[0]), "+f"((d)[1]), "+f"((d)[2]), "+f"((d)[3])               \
        : "r"((a)[0]), "r"((a)[1]), "r"((a)[2]), "r"((a)[3]),                  \
          "r"(b0), "r"(b1))

#define LDSM_X4(r, addr)                                                       \
    asm volatile("ldmatrix.sync.aligned.m8n8.x4.shared.b16 {%0,%1,%2,%3}, [%4];" \
        : "=r"((r)[0]), "=r"((r)[1]), "=r"((r)[2]), "=r"((r)[3]) : "r"(addr))

#define STSM_X4(addr, r0, r1, r2, r3)                                          \
    asm volatile("stmatrix.sync.aligned.m8n8.x4.shared.b16 [%0], {%1,%2,%3,%4};" \
        :: "r"(addr), "r"(r0), "r"(r1), "r"(r2), "r"(r3) : "memory")

#define ONES2 0x3C003C00u
#define QSCALE 0.18033688011112042f

// ---------------------------------------------------------------------------
// cvt kernel: fp32 inputs -> fp16 buffers.
// ---------------------------------------------------------------------------
#define CVT_TOTAL (NB * NS * ND * 2 + ND * ND * 2)

__global__ __launch_bounds__(256) void cvt_kernel(
    const float* __restrict__ q, const float* __restrict__ k,
    const float* __restrict__ wq, const float* __restrict__ wk)
{
    const int idx = (blockIdx.x * 256 + threadIdx.x) * 8;
    const float* src;
    __half* dst;
    int off;
    if (idx < NB * NS * ND) {
        src = q; dst = g_hQin; off = idx;
    } else if (idx < 2 * NB * NS * ND) {
        src = k; dst = g_hKin; off = idx - NB * NS * ND;
    } else if (idx < 2 * NB * NS * ND + ND * ND) {
        src = wq; dst = g_hWq; off = idx - 2 * NB * NS * ND;
    } else {
        src = wk; dst = g_hWk; off = idx - 2 * NB * NS * ND - ND * ND;
    }
    float4 f0 = *(const float4*)(src + off);
    float4 f1 = *(const float4*)(src + off + 4);
    uint2 o0, o1;
    *(__half2*)&o0.x = __floats2half2_rn(f0.x, f0.y);
    *(__half2*)&o0.y = __floats2half2_rn(f0.z, f0.w);
    *(__half2*)&o1.x = __floats2half2_rn(f1.x, f1.y);
    *(__half2*)&o1.y = __floats2half2_rn(f1.z, f1.w);
    *(uint4*)(dst + off) = make_uint4(o0.x, o0.y, o1.x, o1.y);
}

// ---------------------------------------------------------------------------
// Projection GEMM (fp16 mma + ldmatrix, 4x2 warp layout) — unchanged R13.
// ---------------------------------------------------------------------------
#define PJ_H 40
#define PJ_BUF (128 * PJ_H)
#define PJ_SMEM_TOTAL (4 * PJ_BUF * 2)                 // 40,960 B

__global__ __launch_bounds__(256, 2) void proj_mma_kernel(
    const float* __restrict__ bq_in, const float* __restrict__ bk_in)
{
    const int z = blockIdx.z;
    const __half* __restrict__ X = z ? g_hKin : g_hQin;
    const __half* __restrict__ W = z ? g_hWk : g_hWq;
    const float* __restrict__ bias = z ? bk_in : bq_in;
    const float scale = z ? 1.0f : QSCALE;
    __half* __restrict__ Out = z ? g_K : g_Q;

    extern __shared__ __half pjs[];
    __half* Xs = pjs;
    __half* Ws = pjs + 2 * PJ_BUF;
    const uint32_t sb_x = smem_u32(Xs);
    const uint32_t sb_w = smem_u32(Ws);

    const int tid = threadIdx.x;
    const int lane = tid & 31, wid = tid >> 5;
    const int lq = lane & 3, lg = lane >> 2;
    const int wm = wid >> 1, wn = wid & 1;
    const int n0 = blockIdx.x * 128, m0 = blockIdx.y * 128;

    const int lrow = (lane & 7) + ((lane >> 3) & 1) * 8;
    const int lrowB = (lane & 7) + ((lane >> 4) & 1) * 8;
    const uint32_t lofA0 = (uint32_t)(((wm * 32 + lrow) * PJ_H + ((lane >> 4) & 1) * 8) * 2);
    const uint32_t lofA1 = (uint32_t)(((wm * 32 + 16 + lrow) * PJ_H + ((lane >> 4) & 1) * 8) * 2);
    const uint32_t lofB = (uint32_t)(((wn * 64 + lrowB) * PJ_H + ((lane >> 3) & 1) * 8) * 2);

    auto prefetch = [&](int st, int kb) {
        if (tid < 128) {
            uint32_t xs = sb_x + (uint32_t)((st * PJ_BUF + tid * PJ_H) * 2);
            const __half* xg = X + (size_t)(m0 + tid) * ND + kb;
#pragma unroll
            for (int i = 0; i < 4; i++) cp16(xs + i * 16, xg + i * 8);
        } else {
            int r = tid - 128;
            uint32_t ws = sb_w + (uint32_t)((st * PJ_BUF + r * PJ_H) * 2);
            const __half* wg = W + (size_t)(n0 + r) * ND + kb;
#pragma unroll
            for (int i = 0; i < 4; i++) cp16(ws + i * 16, wg + i * 8);
        }
    };

    float acc[2][8][4];
#pragma unroll
    for (int mt = 0; mt < 2; mt++)
#pragma unroll
        for (int nt = 0; nt < 8; nt++)
#pragma unroll
            for (int j = 0; j < 4; j++) acc[mt][nt][j] = 0.0f;

    prefetch(0, 0);
    CP_COMMIT();

    for (int kb_i = 0; kb_i < ND / 32; kb_i++) {
        if (kb_i + 1 < ND / 32) prefetch((kb_i + 1) & 1, (kb_i + 1) * 32);
        CP_COMMIT();
        CP_WAIT1();
        __syncthreads();

        const uint32_t xb = sb_x + (uint32_t)((kb_i & 1) * PJ_BUF * 2);
        const uint32_t wb = sb_w + (uint32_t)((kb_i & 1) * PJ_BUF * 2) + lofB;
#pragma unroll
        for (int s = 0; s < 2; s++) {
            uint32_t a0[4], a1[4];
            LDSM_X4(a0, xb + lofA0 + s * 32);
            LDSM_X4(a1, xb + lofA1 + s * 32);
#pragma unroll
            for (int ntp = 0; ntp < 4; ntp++) {
                uint32_t b[4];
                LDSM_X4(b, wb + ntp * (16 * PJ_H * 2) + s * 32);
                MMA_F16(acc[0][2 * ntp], a0, b[0], b[1]);
                MMA_F16(acc[0][2 * ntp + 1], a0, b[2], b[3]);
                MMA_F16(acc[1][2 * ntp], a1, b[0], b[1]);
                MMA_F16(acc[1][2 * ntp + 1], a1, b[2], b[3]);
            }
        }
        __syncthreads();
    }

#pragma unroll
    for (int mt = 0; mt < 2; mt++) {
        const int m_lo = m0 + wm * 32 + mt * 16 + lg;
        const int b_lo = m_lo >> 11, s_lo = m_lo & 2047;
        const int m_hi = m_lo + 8;
        const int b_hi = m_hi >> 11, s_hi = m_hi & 2047;
#pragma unroll
        for (int nt = 0; nt < 8; nt++) {
            int n = n0 + wn * 64 + nt * 8 + 2 * lq;
            float2 bb = *(const float2*)&bias[n];
            int h = n >> 6, hd = n & 63;
            __half2 o0 = __floats2half2_rn((acc[mt][nt][0] + bb.x) * scale,
                                           (acc[mt][nt][1] + bb.y) * scale);
            __half2 o1 = __floats2half2_rn((acc[mt][nt][2] + bb.x) * scale,
                                           (acc[mt][nt][3] + bb.y) * scale);
            *(__half2*)&Out[((size_t)(b_lo * NH + h) * NS + s_lo) * NHD + hd] = o0;
            *(__half2*)&Out[((size_t)(b_hi * NH + h) * NS + s_hi) * NHD + hd] = o1;
        }
    }
}

// ---------------------------------------------------------------------------
// Score kernel (fp16 mma, 4x2 warp layout) — unchanged R13.
// SMEM: Qs[128][72]h | Ks[2][128][72]h | stg[8][32][72]h   = 92,160 B
// ---------------------------------------------------------------------------
#define QS_H 72
#define KS_OFF  (128 * QS_H * 2)
#define STG_OFF (KS_OFF + 2 * 128 * QS_H * 2)
#define ST2 72
#define SC_SMEM_TOTAL (STG_OFF + 8 * 32 * ST2 * 2)     // 92,160 B

__global__ __launch_bounds__(256, 2) void score_kernel()
{
    extern __shared__ char smem[];
    __half* Qs = (__half*)smem;
    __half* Ks = (__half*)(smem + KS_OFF);
    __half* stgall = (__half*)(smem + STG_OFF);
    const uint32_t sb_q = smem_u32(Qs);
    const uint32_t sb_k = smem_u32(Ks);

    const int tid = threadIdx.x;
    const int lane = tid & 31;
    const int wid = tid >> 5;
    const int lq = lane & 3;
    const int lg = lane >> 2;
    const int wm = wid >> 1, wn = wid & 1;
    const int bh = blockIdx.x;
    const int q0 = blockIdx.y * 128;

    __half* stgw = stgall + wid * 32 * ST2;

    const int lrowA = (lane & 7) + ((lane >> 3) & 1) * 8;
    const int lrowB = (lane & 7) + ((lane >> 4) & 1) * 8;
    const uint32_t lofA0 = (uint32_t)(((wm * 32 + lrowA) * QS_H + ((lane >> 4) & 1) * 8) * 2);
    const uint32_t lofA1 = (uint32_t)(((wm * 32 + 16 + lrowA) * QS_H + ((lane >> 4) & 1) * 8) * 2);
    const uint32_t lofB = (uint32_t)(((wn * 64 + lrowB) * QS_H + ((lane >> 3) & 1) * 8) * 2);
    const uint32_t sb_stg = smem_u32(stgw)
        + (uint32_t)((((lane & 7) + ((lane >> 4) & 1) * 8) * ST2
                      + ((lane >> 3) & 1) * 8) * 2);

    const int r_ld = tid >> 1;
    const int c_ld = (tid & 1) * 32;
    auto prefetchK = [&](int st, int kt) {
        uint32_t ks = sb_k + (uint32_t)((st * 128 * QS_H + r_ld * QS_H + c_ld) * 2);
        const __half* kg = g_K + ((size_t)bh * NS + kt * 128 + r_ld) * NHD + c_ld;
#pragma unroll
        for (int i = 0; i < 4; i++) cp16(ks + i * 16, kg + i * 8);
    };

    prefetchK(0, 0);
    CP_COMMIT();
    {
        uint32_t qs = sb_q + (uint32_t)((r_ld * QS_H + c_ld) * 2);
        const __half* qg = g_Q + ((size_t)bh * NS + q0 + r_ld) * NHD + c_ld;
#pragma unroll
        for (int i = 0; i < 4; i++) cp16(qs + i * 16, qg + i * 8);
    }
    CP_COMMIT();
    CP_WAIT0();
    __syncthreads();

    uint32_t afr[4][2][4];
#pragma unroll
    for (int s = 0; s < 4; s++) {
        LDSM_X4(afr[s][0], sb_q + lofA0 + s * 32);
        LDSM_X4(afr[s][1], sb_q + lofA1 + s * 32);
    }

    float accrs[2][4];
#pragma unroll
    for (int mt = 0; mt < 2; mt++)
#pragma unroll
        for (int j = 0; j < 4; j++) accrs[mt][j] = 0.0f;

    for (int kt = 0; kt < NS / 128; kt++) {
        if (kt + 1 < NS / 128) prefetchK((kt + 1) & 1, kt + 1);
        CP_COMMIT();
        CP_WAIT1();
        __syncthreads();

        const uint32_t kb = sb_k + (uint32_t)((kt & 1) * 128 * QS_H * 2) + lofB;

        float acc[2][8][4];
#pragma unroll
        for (int mt = 0; mt < 2; mt++)
#pragma unroll
            for (int nt = 0; nt < 8; nt++)
#pragma unroll
                for (int j = 0; j < 4; j++) acc[mt][nt][j] = 0.0f;

#pragma unroll
        for (int s = 0; s < 4; s++) {
#pragma unroll
            for (int ntp = 0; ntp < 4; ntp++) {
                uint32_t b[4];
                LDSM_X4(b, kb + ntp * (16 * QS_H * 2) + s * 32);
                MMA_F16(acc[0][2 * ntp], afr[s][0], b[0], b[1]);
                MMA_F16(acc[0][2 * ntp + 1], afr[s][0], b[2], b[3]);
                MMA_F16(acc[1][2 * ntp], afr[s][1], b[0], b[1]);
                MMA_F16(acc[1][2 * ntp + 1], afr[s][1], b[2], b[3]);
            }
        }

#pragma unroll
        for (int mt = 0; mt < 2; mt++) {
            uint32_t h2[16];
#pragma unroll
            for (int nt = 0; nt < 8; nt++) {
                float e0 = ex2a(acc[mt][nt][0]);
                float e1 = ex2a(acc[mt][nt][1]);
                float e2 = ex2a(acc[mt][nt][2]);
                float e3 = ex2a(acc[mt][nt][3]);
                __half2 ha = __floats2half2_rn(e0, e1);
                __half2 hb = __floats2half2_rn(e2, e3);
                h2[2 * nt] = *(uint32_t*)&ha;
                h2[2 * nt + 1] = *(uint32_t*)&hb;
            }
#pragma unroll
            for (int p = 0; p < 4; p++) {
                uint32_t a[4] = {h2[4 * p], h2[4 * p + 1],
                                 h2[4 * p + 2], h2[4 * p + 3]};
                MMA_F16(accrs[mt], a, ONES2, ONES2);
            }
#pragma unroll
            for (int p = 0; p < 4; p++) {
                STSM_X4(sb_stg + (uint32_t)(mt * 16 * ST2 * 2) + p * 32,
                        h2[4 * p], h2[4 * p + 2],
                        h2[4 * p + 1], h2[4 * p + 3]);
            }
        }
        __syncwarp();
#pragma unroll
        for (int rr = 0; rr < 8; rr++) {
            int row = rr * 4 + (lane >> 3);
            uint4 v = *(uint4*)&stgw[row * ST2 + (lane & 7) * 8];
            *(uint4*)&g_E[((size_t)bh * NS + q0 + wm * 32 + row) * NS
                          + kt * 128 + wn * 64 + (lane & 7) * 8] = v;
        }
        __syncthreads();
    }

    // Combine wn-partials; write Linv (with /16 folded).
    float* rsb = (float*)stgall;
    if (lq == 0) {
#pragma unroll
        for (int mt = 0; mt < 2; mt++) {
            int r = wm * 32 + mt * 16 + lg;
            rsb[wn * 128 + r] = accrs[mt][0];
            rsb[wn * 128 + r + 8] = accrs[mt][2];
        }
    }
    __syncthreads();
    if (tid < 128) {
        g_Linv[bh * NS + q0 + tid] = 0.0625f / (rsb[tid] + rsb[128 + tid]);
    }
}

// ---------------------------------------------------------------------------
// Finalize: out[b,q,k] = sum_h E[b,h,q,k] * Linv[b,h,q]   (pure streaming)
//   REVERSED block->row order: score finishes with high-qt tiles, so the
//   last-written (high-q) E rows are L2-resident; consume them first.
// ---------------------------------------------------------------------------
__global__ __launch_bounds__(256) void finalize_kernel(float* __restrict__ out)
{
    const int tid = threadIdx.x;
    const int bq = (NB * NS - 1) - blockIdx.x;     // reverse order
    const int b = bq >> 11, q = bq & 2047;

    float acc[8];
#pragma unroll
    for (int j = 0; j < 8; j++) acc[j] = 0.0f;

    for (int h = 0; h < NH; h++) {
        const int bhh = b * NH + h;
        const float w = g_Linv[(bhh << 11) + q];
        const uint4* __restrict__ Ep =
            (const uint4*)(g_E + ((size_t)bhh * NS + q) * NS) + tid;
        uint4 v = *Ep;
        const __half2* hp = (const __half2*)&v;
#pragma unroll
        for (int j = 0; j < 4; j++) {
            float2 f = __half22float2(hp[j]);
            acc[2 * j] += f.x * w;
            acc[2 * j + 1] += f.y * w;
        }
    }

    float4* __restrict__ Op = (float4*)(out + (size_t)bq * NS);
    Op[tid * 2 + 0] = make_float4(acc[0], acc[1], acc[2], acc[3]);
    Op[tid * 2 + 1] = make_float4(acc[4], acc[5], acc[6], acc[7]);
}

// ---------------------------------------------------------------------------
extern "C" void kernel_launch(void* const* d_in, const int* in_sizes, int n_in,
                              void* d_out, int out_size)
{
    const float* query = (const float*)d_in[0];
    const float* key   = (const float*)d_in[1];
    const float* Wq    = (const float*)d_in[2];
    const float* bq    = (const float*)d_in[3];
    const float* Wk    = (const float*)d_in[4];
    const float* bk    = (const float*)d_in[5];
    float* out = (float*)d_out;

    cudaFuncSetAttribute(proj_mma_kernel,
                         cudaFuncAttributeMaxDynamicSharedMemorySize,
                         PJ_SMEM_TOTAL);
    cudaFuncSetAttribute(score_kernel,
                         cudaFuncAttributeMaxDynamicSharedMemorySize,
                         SC_SMEM_TOTAL);

    cvt_kernel<<<CVT_TOTAL / (256 * 8), 256>>>(query, key, Wq, Wk);
    proj_mma_kernel<<<dim3(ND / 128, (NB * NS) / 128, 2), 256, PJ_SMEM_TOTAL>>>(bq, bk);
    score_kernel<<<dim3(NB * NH, NS / 128), 256, SC_SMEM_TOTAL>>>();
    finalize_kernel<<<NB * NS, 256>>>(out);
}

// round 17
// speedup vs baseline: 1.7030x; 1.0359x over previous
#include <cuda_runtime.h>
#include <cuda_fp16.h>
#include <cstdint>

#define NB 2
#define NS 2048
#define ND 1024
#define NH 16
#define NHD 64

// fp16 copies of the inputs (filled by cvt_kernel)
__device__ __half g_hQin[NB * NS * ND];
__device__ __half g_hKin[NB * NS * ND];
__device__ __half g_hWq[ND * ND];
__device__ __half g_hWk[ND * ND];

// Scratch — Q/K projections stored as fp16 (Q pre-scaled by 0.125*log2e).
__device__ __half g_Q[NB * NH * NS * NHD];
__device__ __half g_K[NB * NH * NS * NHD];
__device__ __half g_E[(size_t)NB * NH * NS * NS];     // 268 MB fp16 2^scores
__device__ float  g_Linv[NB * NH * NS];               // 1/(16*rowsum)

// ---------------------------------------------------------------------------
__device__ __forceinline__ uint32_t smem_u32(const void* p) {
    uint32_t a;
    asm("{ .reg .u64 t; cvta.to.shared.u64 t, %1; cvt.u32.u64 %0, t; }"
        : "=r"(a) : "l"(p));
    return a;
}
__device__ __forceinline__ void cp16(uint32_t s, const void* g) {
    asm volatile("cp.async.cg.shared.global [%0], [%1], 16;" :: "r"(s), "l"(g));
}
#define CP_COMMIT() asm volatile("cp.async.commit_group;" ::: "memory")
#define CP_WAIT1()  asm volatile("cp.async.wait_group 1;" ::: "memory")
#define CP_WAIT0()  asm volatile("cp.async.wait_group 0;" ::: "memory")

#define MMA_F16(d, a, b0, b1)                                                  \
    asm volatile(                                                              \
        "mma.sync.aligned.m16n8k16.row.col.f32.f16.f16.f32 "                   \
        "{%0,%1,%2,%3}, {%4,%5,%6,%7}, {%8,%9}, {%0,%1,%2,%3};"                \
        : "+f"((d)[0]), "+f"((d)[1]), "+f"((d)[2]), "+f"((d)[3])               \
        : "r"((a)[0]), "r"((a)[1]), "r"((a)[2]), "r"((a)[3]),                  \
          "r"(b0), "r"(b1))

#define LDSM_X4(r, addr)                                                       \
    asm volatile("ldmatrix.sync.aligned.m8n8.x4.shared.b16 {%0,%1,%2,%3}, [%4];" \
        : "=r"((r)[0]), "=r"((r)[1]), "=r"((r)[2]), "=r"((r)[3]) : "r"(addr))

#define STSM_X4(addr, r0, r1, r2, r3)                                          \
    asm volatile("stmatrix.sync.aligned.m8n8.x4.shared.b16 [%0], {%1,%2,%3,%4};" \
        :: "r"(addr), "r"(r0), "r"(r1), "r"(r2), "r"(r3) : "memory")

// packed fp16x2 2^x
__device__ __forceinline__ uint32_t ex2_h2(uint32_t x) {
    uint32_t y;
    asm("ex2.approx.f16x2 %0, %1;" : "=r"(y) : "r"(x));
    return y;
}

#define ONES2 0x3C003C00u
#define QSCALE 0.18033688011112042f

// ---------------------------------------------------------------------------
// cvt kernel: fp32 inputs -> fp16 buffers.
// ---------------------------------------------------------------------------
#define CVT_TOTAL (NB * NS * ND * 2 + ND * ND * 2)

__global__ __launch_bounds__(256) void cvt_kernel(
    const float* __restrict__ q, const float* __restrict__ k,
    const float* __restrict__ wq, const float* __restrict__ wk)
{
    const int idx = (blockIdx.x * 256 + threadIdx.x) * 8;
    const float* src;
    __half* dst;
    int off;
    if (idx < NB * NS * ND) {
        src = q; dst = g_hQin; off = idx;
    } else if (idx < 2 * NB * NS * ND) {
        src = k; dst = g_hKin; off = idx - NB * NS * ND;
    } else if (idx < 2 * NB * NS * ND + ND * ND) {
        src = wq; dst = g_hWq; off = idx - 2 * NB * NS * ND;
    } else {
        src = wk; dst = g_hWk; off = idx - 2 * NB * NS * ND - ND * ND;
    }
    float4 f0 = *(const float4*)(src + off);
    float4 f1 = *(const float4*)(src + off + 4);
    uint2 o0, o1;
    *(__half2*)&o0.x = __floats2half2_rn(f0.x, f0.y);
    *(__half2*)&o0.y = __floats2half2_rn(f0.z, f0.w);
    *(__half2*)&o1.x = __floats2half2_rn(f1.x, f1.y);
    *(__half2*)&o1.y = __floats2half2_rn(f1.z, f1.w);
    *(uint4*)(dst + off) = make_uint4(o0.x, o0.y, o1.x, o1.y);
}

// ---------------------------------------------------------------------------
// Projection GEMM (fp16 mma + ldmatrix, 4x2 warp layout) — unchanged R13.
// ---------------------------------------------------------------------------
#define PJ_H 40
#define PJ_BUF (128 * PJ_H)
#define PJ_SMEM_TOTAL (4 * PJ_BUF * 2)                 // 40,960 B

__global__ __launch_bounds__(256, 2) void proj_mma_kernel(
    const float* __restrict__ bq_in, const float* __restrict__ bk_in)
{
    const int z = blockIdx.z;
    const __half* __restrict__ X = z ? g_hKin : g_hQin;
    const __half* __restrict__ W = z ? g_hWk : g_hWq;
    const float* __restrict__ bias = z ? bk_in : bq_in;
    const float scale = z ? 1.0f : QSCALE;
    __half* __restrict__ Out = z ? g_K : g_Q;

    extern __shared__ __half pjs[];
    __half* Xs = pjs;
    __half* Ws = pjs + 2 * PJ_BUF;
    const uint32_t sb_x = smem_u32(Xs);
    const uint32_t sb_w = smem_u32(Ws);

    const int tid = threadIdx.x;
    const int lane = tid & 31, wid = tid >> 5;
    const int lq = lane & 3, lg = lane >> 2;
    const int wm = wid >> 1, wn = wid & 1;
    const int n0 = blockIdx.x * 128, m0 = blockIdx.y * 128;

    const int lrow = (lane & 7) + ((lane >> 3) & 1) * 8;
    const int lrowB = (lane & 7) + ((lane >> 4) & 1) * 8;
    const uint32_t lofA0 = (uint32_t)(((wm * 32 + lrow) * PJ_H + ((lane >> 4) & 1) * 8) * 2);
    const uint32_t lofA1 = (uint32_t)(((wm * 32 + 16 + lrow) * PJ_H + ((lane >> 4) & 1) * 8) * 2);
    const uint32_t lofB = (uint32_t)(((wn * 64 + lrowB) * PJ_H + ((lane >> 3) & 1) * 8) * 2);

    auto prefetch = [&](int st, int kb) {
        if (tid < 128) {
            uint32_t xs = sb_x + (uint32_t)((st * PJ_BUF + tid * PJ_H) * 2);
            const __half* xg = X + (size_t)(m0 + tid) * ND + kb;
#pragma unroll
            for (int i = 0; i < 4; i++) cp16(xs + i * 16, xg + i * 8);
        } else {
            int r = tid - 128;
            uint32_t ws = sb_w + (uint32_t)((st * PJ_BUF + r * PJ_H) * 2);
            const __half* wg = W + (size_t)(n0 + r) * ND + kb;
#pragma unroll
            for (int i = 0; i < 4; i++) cp16(ws + i * 16, wg + i * 8);
        }
    };

    float acc[2][8][4];
#pragma unroll
    for (int mt = 0; mt < 2; mt++)
#pragma unroll
        for (int nt = 0; nt < 8; nt++)
#pragma unroll
            for (int j = 0; j < 4; j++) acc[mt][nt][j] = 0.0f;

    prefetch(0, 0);
    CP_COMMIT();

    for (int kb_i = 0; kb_i < ND / 32; kb_i++) {
        if (kb_i + 1 < ND / 32) prefetch((kb_i + 1) & 1, (kb_i + 1) * 32);
        CP_COMMIT();
        CP_WAIT1();
        __syncthreads();

        const uint32_t xb = sb_x + (uint32_t)((kb_i & 1) * PJ_BUF * 2);
        const uint32_t wb = sb_w + (uint32_t)((kb_i & 1) * PJ_BUF * 2) + lofB;
#pragma unroll
        for (int s = 0; s < 2; s++) {
            uint32_t a0[4], a1[4];
            LDSM_X4(a0, xb + lofA0 + s * 32);
            LDSM_X4(a1, xb + lofA1 + s * 32);
#pragma unroll
            for (int ntp = 0; ntp < 4; ntp++) {
                uint32_t b[4];
                LDSM_X4(b, wb + ntp * (16 * PJ_H * 2) + s * 32);
                MMA_F16(acc[0][2 * ntp], a0, b[0], b[1]);
                MMA_F16(acc[0][2 * ntp + 1], a0, b[2], b[3]);
                MMA_F16(acc[1][2 * ntp], a1, b[0], b[1]);
                MMA_F16(acc[1][2 * ntp + 1], a1, b[2], b[3]);
            }
        }
        __syncthreads();
    }

#pragma unroll
    for (int mt = 0; mt < 2; mt++) {
        const int m_lo = m0 + wm * 32 + mt * 16 + lg;
        const int b_lo = m_lo >> 11, s_lo = m_lo & 2047;
        const int m_hi = m_lo + 8;
        const int b_hi = m_hi >> 11, s_hi = m_hi & 2047;
#pragma unroll
        for (int nt = 0; nt < 8; nt++) {
            int n = n0 + wn * 64 + nt * 8 + 2 * lq;
            float2 bb = *(const float2*)&bias[n];
            int h = n >> 6, hd = n & 63;
            __half2 o0 = __floats2half2_rn((acc[mt][nt][0] + bb.x) * scale,
                                           (acc[mt][nt][1] + bb.y) * scale);
            __half2 o1 = __floats2half2_rn((acc[mt][nt][2] + bb.x) * scale,
                                           (acc[mt][nt][3] + bb.y) * scale);
            *(__half2*)&Out[((size_t)(b_lo * NH + h) * NS + s_lo) * NHD + hd] = o0;
            *(__half2*)&Out[((size_t)(b_hi * NH + h) * NS + s_hi) * NHD + hd] = o1;
        }
    }
}

// ---------------------------------------------------------------------------
// Score kernel: fp16 mma, 4x2 warp layout, 3-stage K pipeline (no trailing
// barrier per tile), f16x2 ex2 epilogue.
// SMEM: Qs[128][72]h | Ks[3][128][72]h | stg[8][32][72]h   = 110,592 B
// ---------------------------------------------------------------------------
#define QS_H 72
#define KBUF (128 * QS_H * 2)                          // 18,432 B
#define KS_OFF  KBUF
#define STG_OFF (KS_OFF + 3 * KBUF)                    // 73,728 B
#define ST2 72
#define SC_SMEM_TOTAL (STG_OFF + 8 * 32 * ST2 * 2)     // 110,592 B

__global__ __launch_bounds__(256, 2) void score_kernel()
{
    extern __shared__ char smem[];
    __half* Qs = (__half*)smem;
    __half* stgall = (__half*)(smem + STG_OFF);
    const uint32_t sb_q = smem_u32(Qs);
    const uint32_t sb_k = sb_q + KS_OFF;

    const int tid = threadIdx.x;
    const int lane = tid & 31;
    const int wid = tid >> 5;
    const int lq = lane & 3;
    const int lg = lane >> 2;
    const int wm = wid >> 1, wn = wid & 1;
    const int bh = blockIdx.x;
    const int q0 = blockIdx.y * 128;

    __half* stgw = stgall + wid * 32 * ST2;

    const int lrowA = (lane & 7) + ((lane >> 3) & 1) * 8;
    const int lrowB = (lane & 7) + ((lane >> 4) & 1) * 8;
    const uint32_t lofA0 = (uint32_t)(((wm * 32 + lrowA) * QS_H + ((lane >> 4) & 1) * 8) * 2);
    const uint32_t lofA1 = (uint32_t)(((wm * 32 + 16 + lrowA) * QS_H + ((lane >> 4) & 1) * 8) * 2);
    const uint32_t lofB = (uint32_t)(((wn * 64 + lrowB) * QS_H + ((lane >> 3) & 1) * 8) * 2);
    const uint32_t sb_stg = smem_u32(stgw)
        + (uint32_t)((((lane & 7) + ((lane >> 4) & 1) * 8) * ST2
                      + ((lane >> 3) & 1) * 8) * 2);

    const int r_ld = tid >> 1;
    const int c_ld = (tid & 1) * 32;
    auto prefetchK = [&](int st, int kt) {
        uint32_t ks = sb_k + (uint32_t)(st * KBUF + (r_ld * QS_H + c_ld) * 2);
        const __half* kg = g_K + ((size_t)bh * NS + kt * 128 + r_ld) * NHD + c_ld;
#pragma unroll
        for (int i = 0; i < 4; i++) cp16(ks + i * 16, kg + i * 8);
    };

    // Pipeline prologue: K0 | Q | K1 as three commit-groups.
    prefetchK(0, 0);
    CP_COMMIT();
    {
        uint32_t qs = sb_q + (uint32_t)((r_ld * QS_H + c_ld) * 2);
        const __half* qg = g_Q + ((size_t)bh * NS + q0 + r_ld) * NHD + c_ld;
#pragma unroll
        for (int i = 0; i < 4; i++) cp16(qs + i * 16, qg + i * 8);
    }
    CP_COMMIT();
    prefetchK(1, 1);
    CP_COMMIT();
    CP_WAIT1();                 // K0 + Q complete (K1 may be in flight)
    __syncthreads();

    uint32_t afr[4][2][4];
#pragma unroll
    for (int s = 0; s < 4; s++) {
        LDSM_X4(afr[s][0], sb_q + lofA0 + s * 32);
        LDSM_X4(afr[s][1], sb_q + lofA1 + s * 32);
    }

    float accrs[2][4];
#pragma unroll
    for (int mt = 0; mt < 2; mt++)
#pragma unroll
        for (int j = 0; j < 4; j++) accrs[mt][j] = 0.0f;

    for (int kt = 0; kt < NS / 128; kt++) {
        if (kt > 0) {
            CP_WAIT1();         // group carrying K(kt) complete
            __syncthreads();    // also: everyone done reading buf reused below
        }
        // depth-2 prefetch into the buffer last read at iteration kt-1
        if (kt + 2 < NS / 128) prefetchK((kt + 2) % 3, kt + 2);
        CP_COMMIT();            // unconditional: keeps group accounting uniform

        const uint32_t kb = sb_k + (uint32_t)((kt % 3) * KBUF) + lofB;

        float acc[2][8][4];
#pragma unroll
        for (int mt = 0; mt < 2; mt++)
#pragma unroll
            for (int nt = 0; nt < 8; nt++)
#pragma unroll
                for (int j = 0; j < 4; j++) acc[mt][nt][j] = 0.0f;

#pragma unroll
        for (int s = 0; s < 4; s++) {
#pragma unroll
            for (int ntp = 0; ntp < 4; ntp++) {
                uint32_t b[4];
                LDSM_X4(b, kb + ntp * (16 * QS_H * 2) + s * 32);
                MMA_F16(acc[0][2 * ntp], afr[s][0], b[0], b[1]);
                MMA_F16(acc[0][2 * ntp + 1], afr[s][0], b[2], b[3]);
                MMA_F16(acc[1][2 * ntp], afr[s][1], b[0], b[1]);
                MMA_F16(acc[1][2 * ntp + 1], afr[s][1], b[2], b[3]);
            }
        }

        // Epilogue: pack scores -> f16x2 ex2 -> rowsum mma + stmatrix staging.
#pragma unroll
        for (int mt = 0; mt < 2; mt++) {
            uint32_t h2[16];
#pragma unroll
            for (int nt = 0; nt < 8; nt++) {
                __half2 s0 = __floats2half2_rn(acc[mt][nt][0], acc[mt][nt][1]);
                __half2 s1 = __floats2half2_rn(acc[mt][nt][2], acc[mt][nt][3]);
                h2[2 * nt] = ex2_h2(*(uint32_t*)&s0);
                h2[2 * nt + 1] = ex2_h2(*(uint32_t*)&s1);
            }
#pragma unroll
            for (int p = 0; p < 4; p++) {
                uint32_t a[4] = {h2[4 * p], h2[4 * p + 1],
                                 h2[4 * p + 2], h2[4 * p + 3]};
                MMA_F16(accrs[mt], a, ONES2, ONES2);
            }
#pragma unroll
            for (int p = 0; p < 4; p++) {
                STSM_X4(sb_stg + (uint32_t)(mt * 16 * ST2 * 2) + p * 32,
                        h2[4 * p], h2[4 * p + 2],
                        h2[4 * p + 1], h2[4 * p + 3]);
            }
        }
        __syncwarp();
#pragma unroll
        for (int rr = 0; rr < 8; rr++) {
            int row = rr * 4 + (lane >> 3);
            uint4 v = *(uint4*)&stgw[row * ST2 + (lane & 7) * 8];
            *(uint4*)&g_E[((size_t)bh * NS + q0 + wm * 32 + row) * NS
                          + kt * 128 + wn * 64 + (lane & 7) * 8] = v;
        }
        // no trailing __syncthreads: protected by top-of-next-iter barrier
    }

    __syncthreads();   // all warps done with their stg regions before aliasing

    // Combine wn-partials; write Linv (with /16 folded).
    float* rsb = (float*)stgall;
    if (lq == 0) {
#pragma unroll
        for (int mt = 0; mt < 2; mt++) {
            int r = wm * 32 + mt * 16 + lg;
            rsb[wn * 128 + r] = accrs[mt][0];
            rsb[wn * 128 + r + 8] = accrs[mt][2];
        }
    }
    __syncthreads();
    if (tid < 128) {
        g_Linv[bh * NS + q0 + tid] = 0.0625f / (rsb[tid] + rsb[128 + tid]);
    }
}

// ---------------------------------------------------------------------------
// Finalize: out[b,q,k] = sum_h E[b,h,q,k] * Linv[b,h,q]   (pure streaming)
// ---------------------------------------------------------------------------
__global__ __launch_bounds__(256) void finalize_kernel(float* __restrict__ out)
{
    const int tid = threadIdx.x;
    const int bq = (NB * NS - 1) - blockIdx.x;
    const int b = bq >> 11, q = bq & 2047;

    float acc[8];
#pragma unroll
    for (int j = 0; j < 8; j++) acc[j] = 0.0f;

    for (int h = 0; h < NH; h++) {
        const int bhh = b * NH + h;
        const float w = g_Linv[(bhh << 11) + q];
        const uint4* __restrict__ Ep =
            (const uint4*)(g_E + ((size_t)bhh * NS + q) * NS) + tid;
        uint4 v = *Ep;
        const __half2* hp = (const __half2*)&v;
#pragma unroll
        for (int j = 0; j < 4; j++) {
            float2 f = __half22float2(hp[j]);
            acc[2 * j] += f.x * w;
            acc[2 * j + 1] += f.y * w;
        }
    }

    float4* __restrict__ Op = (float4*)(out + (size_t)bq * NS);
    Op[tid * 2 + 0] = make_float4(acc[0], acc[1], acc[2], acc[3]);
    Op[tid * 2 + 1] = make_float4(acc[4], acc[5], acc[6], acc[7]);
}

// ---------------------------------------------------------------------------
extern "C" void kernel_launch(void* const* d_in, const int* in_sizes, int n_in,
                              void* d_out, int out_size)
{
    const float* query = (const float*)d_in[0];
    const float* key   = (const float*)d_in[1];
    const float* Wq    = (const float*)d_in[2];
    const float* bq    = (const float*)d_in[3];
    const float* Wk    = (const float*)d_in[4];
    const float* bk    = (const float*)d_in[5];
    float* out = (float*)d_out;

    cudaFuncSetAttribute(proj_mma_kernel,
                         cudaFuncAttributeMaxDynamicSharedMemorySize,
                         PJ_SMEM_TOTAL);
    cudaFuncSetAttribute(score_kernel,
                         cudaFuncAttributeMaxDynamicSharedMemorySize,
                         SC_SMEM_TOTAL);

    cvt_kernel<<<CVT_TOTAL / (256 * 8), 256>>>(query, key, Wq, Wk);
    proj_mma_kernel<<<dim3(ND / 128, (NB * NS) / 128, 2), 256, PJ_SMEM_TOTAL>>>(bq, bk);
    score_kernel<<<dim3(NB * NH, NS / 128), 256, SC_SMEM_TOTAL>>>();
    finalize_kernel<<<NB * NS, 256>>>(out);
}